// round 5
// baseline (speedup 1.0000x reference)
#include <cuda_runtime.h>
#include <cuda_fp16.h>
#include <math.h>
#include <stdint.h>

// Problem constants
constexpr int Bb = 256;    // batch
constexpr int Tt = 512;    // seq len
constexpr int Ii = 256;    // input size
constexpr int Hh = 512;    // hidden size
constexpr int Oo = 256;    // output size
constexpr int G4 = 4 * Hh; // 2048 packed gate width, n = j*4 + g (0=f,1=i,2=c,3=o)

// ---------------------------------------------------------------------------
// Device scratch
// ---------------------------------------------------------------------------
__device__ __half g_gx[(size_t)Tt * Bb * G4];   // 512 MB: input projections fp16, m = t*B+b
__device__ __half g_xh[(size_t)Tt * Bb * Ii];   // 64 MB: x fp16, [m][k]
__device__ __half g_Wxh[(size_t)G4 * Ii];       // W_x packed [n][k] fp16
__device__ __half g_Whh[(size_t)G4 * Hh];       // W_h packed [n][k] fp16
__device__ float  g_biasp[G4];                  // bias packed [n]
__device__ __half g_hh[2][Bb * Hh];             // double-buffered hidden (fp16)
__device__ unsigned g_ctr;                      // grid barrier counter

// ---------------------------------------------------------------------------
// PTX helpers (base PTX only: valid at compute_103 virtual arch)
// ---------------------------------------------------------------------------
__device__ __forceinline__ uint32_t smem_u32(const void* p) {
    uint32_t a;
    asm("{ .reg .u64 t; cvta.to.shared.u64 t, %1; cvt.u32.u64 %0, t; }" : "=r"(a) : "l"(p));
    return a;
}
__device__ __forceinline__ void cp16(uint32_t dst, const void* src) {
    asm volatile("cp.async.cg.shared.global [%0], [%1], 16;" :: "r"(dst), "l"(src));
}
#define CP_COMMIT() asm volatile("cp.async.commit_group;" ::: "memory")
#define CP_WAIT(n)  asm volatile("cp.async.wait_group %0;" :: "n"(n) : "memory")

__device__ __forceinline__ void ldm_x4(uint32_t (&r)[4], uint32_t addr) {
    asm volatile("ldmatrix.sync.aligned.m8n8.x4.shared.b16 {%0,%1,%2,%3}, [%4];"
        : "=r"(r[0]), "=r"(r[1]), "=r"(r[2]), "=r"(r[3]) : "r"(addr));
}
__device__ __forceinline__ void mma16816(float (&c)[4], const uint32_t (&a)[4], const uint32_t* b) {
    asm volatile("mma.sync.aligned.m16n8k16.row.col.f32.f16.f16.f32 "
        "{%0,%1,%2,%3}, {%4,%5,%6,%7}, {%8,%9}, {%0,%1,%2,%3};"
        : "+f"(c[0]), "+f"(c[1]), "+f"(c[2]), "+f"(c[3])
        : "r"(a[0]), "r"(a[1]), "r"(a[2]), "r"(a[3]), "r"(b[0]), "r"(b[1]));
}

// Fast activations (err ~1e-7, below fp16 noise)
__device__ __forceinline__ float ex2f(float x) { float y; asm("ex2.approx.f32 %0, %1;" : "=f"(y) : "f"(x)); return y; }
__device__ __forceinline__ float rcpf(float x) { float y; asm("rcp.approx.f32 %0, %1;" : "=f"(y) : "f"(x)); return y; }
__device__ __forceinline__ float sigf(float x)   { return rcpf(1.0f + ex2f(-1.4426950408889634f * x)); }
__device__ __forceinline__ float tanhf_(float x) { return __fmaf_rn(2.0f, sigf(2.0f * x), -1.0f); }

// SMEM tile geometry: 64 data halves + 8 pad per row -> conflict-free ldmatrix
constexpr int RSTRIDE = 144;                 // bytes per smem row
constexpr int CHUNK_BYTES = 64 * RSTRIDE;    // one 64x64-half chunk = 9216 B

__device__ __forceinline__ uint32_t a_lane_off(int lane) {
    return (uint32_t)(((lane & 7) + ((lane >> 3) & 1) * 8) * RSTRIDE + (lane >> 4) * 16);
}
__device__ __forceinline__ uint32_t b_lane_off(int lane) {
    return (uint32_t)(((lane & 7) + ((lane >> 4) & 1) * 8) * RSTRIDE + ((lane >> 3) & 1) * 16);
}

// ---------------------------------------------------------------------------
// Packing
// ---------------------------------------------------------------------------
__global__ void pack_x(const float* __restrict__ x) {
    size_t e = ((size_t)blockIdx.x * blockDim.x + threadIdx.x) * 4;
    if (e >= (size_t)Tt * Bb * Ii) return;
    int    k  = (int)(e & 255);
    size_t md = e >> 8;
    int    b  = (int)(md & 255);
    int    t  = (int)(md >> 8);
    float4 v = *(const float4*)(x + ((size_t)b * Tt + t) * Ii + k);
    *(__half2*)(g_xh + e)     = __floats2half2_rn(v.x, v.y);
    *(__half2*)(g_xh + e + 2) = __floats2half2_rn(v.z, v.w);
}

__global__ void pack_w(const float* __restrict__ Wf, const float* __restrict__ bf,
                       const float* __restrict__ Wi, const float* __restrict__ bi,
                       const float* __restrict__ Wc, const float* __restrict__ bc,
                       const float* __restrict__ Wo, const float* __restrict__ bo) {
    int k = blockIdx.x;  // 0..767
    for (int n = threadIdx.x; n < G4; n += blockDim.x) {
        int g = n & 3, j = n >> 2;
        const float* W = (g == 0) ? Wf : (g == 1) ? Wi : (g == 2) ? Wc : Wo;
        float v = W[(size_t)k * Hh + j];
        if (k < Ii) g_Wxh[(size_t)n * Ii + k] = __float2half_rn(v);
        else        g_Whh[(size_t)n * Hh + (k - Ii)] = __float2half_rn(v);
        if (k == 0) {
            const float* bp = (g == 0) ? bf : (g == 1) ? bi : (g == 2) ? bc : bo;
            g_biasp[n] = bp[j];
        }
    }
}

__global__ void zero_state() {
    int i = blockIdx.x * blockDim.x + threadIdx.x;
    if (i == 0) g_ctr = 0;
    if (i < Bb * Hh) g_hh[0][i] = __float2half_rn(0.0f);
}

// ---------------------------------------------------------------------------
// Phase 1: gx[m][n] = fp16( sum_k xh[m][k] * Wxh[n][k] + bias[n] )
//   CTA 64(M) x 128(N), 256 thr (8 warps = 2x4), K=256 in 4 cp.async stages.
// ---------------------------------------------------------------------------
constexpr uint32_t P1_A0 = 0,      P1_B0 = 9216;
constexpr uint32_t P1_A1 = 27648,  P1_B1 = 36864;
constexpr int P1_SMEM = 55296;

__global__ void __launch_bounds__(256) phase1_mma() {
    extern __shared__ __align__(128) char smem[];
    const uint32_t sb = smem_u32(smem);
    const int tid = threadIdx.x, lane = tid & 31, wid = tid >> 5;
    const int wm = wid >> 2, wn = wid & 3;
    const int n0 = blockIdx.x * 128;
    const int m0 = blockIdx.y * 64;

    const uint32_t aoff = a_lane_off(lane);
    const uint32_t boff = b_lane_off(lane);

    float acc[2][4][4] = {};

    auto load_stage = [&](int s, uint32_t Ab, uint32_t Bx) {
        const int kb0 = s * 64;
#pragma unroll
        for (int q = 0; q < 2; q++) {
            int i = tid + q * 256, r = i >> 3, g = i & 7;
            cp16(sb + Ab + r * RSTRIDE + g * 16, g_xh + (size_t)(m0 + r) * Ii + kb0 + g * 8);
        }
#pragma unroll
        for (int q = 0; q < 4; q++) {
            int i = tid + q * 256, r = i >> 3, g = i & 7;
            cp16(sb + Bx + r * RSTRIDE + g * 16, g_Wxh + (size_t)(n0 + r) * Ii + kb0 + g * 8);
        }
        CP_COMMIT();
    };
    auto compute = [&](uint32_t Ab, uint32_t Bx) {
#pragma unroll
        for (int kb = 0; kb < 64; kb += 16) {
            uint32_t a[2][4], b[2][4];
#pragma unroll
            for (int mi = 0; mi < 2; mi++)
                ldm_x4(a[mi], sb + Ab + (wm * 32 + mi * 16) * RSTRIDE + kb * 2 + aoff);
#pragma unroll
            for (int bi = 0; bi < 2; bi++)
                ldm_x4(b[bi], sb + Bx + (wn * 32 + bi * 16) * RSTRIDE + kb * 2 + boff);
#pragma unroll
            for (int mi = 0; mi < 2; mi++)
#pragma unroll
                for (int ni = 0; ni < 4; ni++)
                    mma16816(acc[mi][ni], a[mi], &b[ni >> 1][(ni & 1) * 2]);
        }
    };

    load_stage(0, P1_A0, P1_B0);
#pragma unroll
    for (int s = 0; s < 4; s++) {
        if (s < 3) { load_stage(s + 1, (s & 1) ? P1_A0 : P1_A1, (s & 1) ? P1_B0 : P1_B1); CP_WAIT(1); }
        else       { CP_WAIT(0); }
        __syncthreads();
        compute((s & 1) ? P1_A1 : P1_A0, (s & 1) ? P1_B1 : P1_B0);
        __syncthreads();
    }

    // Epilogue: fp16 store with bias
    const int r0 = wm * 32 + (lane >> 2);
    const int c0 = wn * 32 + 2 * (lane & 3);
#pragma unroll
    for (int mi = 0; mi < 2; mi++) {
#pragma unroll
        for (int ni = 0; ni < 4; ni++) {
            const int n = n0 + c0 + ni * 8;
            const float2 bv = *(const float2*)&g_biasp[n];
            const int m = m0 + r0 + mi * 16;
            *(__half2*)(g_gx + (size_t)m * G4 + n) =
                __floats2half2_rn(acc[mi][ni][0] + bv.x, acc[mi][ni][1] + bv.y);
            *(__half2*)(g_gx + (size_t)(m + 8) * G4 + n) =
                __floats2half2_rn(acc[mi][ni][2] + bv.x, acc[mi][ni][3] + bv.y);
        }
    }
}

// ---------------------------------------------------------------------------
// Persistent recurrence: 128 CTAs (32 n-tiles x 4 b-tiles), all 512 steps in
// one kernel. 256 threads = 8 warps (4m x 2n) -> 2 warps/SMSP for latency
// hiding. W_h resident in smem; c in registers; grid spin barrier per step.
// ---------------------------------------------------------------------------
constexpr uint32_t PS_A  = 0;                       // A (h) chunks: 8 x 9216
constexpr uint32_t PS_B  = 8 * CHUNK_BYTES;         // B (Wh) resident: 8 x 9216
constexpr uint32_t PS_GX = 16 * CHUNK_BYTES;        // gx slice: 64 x 64 halves = 8192
constexpr uint32_t PS_CS = PS_GX + 8192;            // Cs exchange: 64 x 68 f32
constexpr int CS_STRIDE = 68;
constexpr int PS_SMEM = PS_CS + 64 * CS_STRIDE * 4; // 173056 B

__global__ void __launch_bounds__(256) lstm_persistent() {
    extern __shared__ __align__(128) char smem[];
    const uint32_t sb = smem_u32(smem);
    float*  Cs  = (float*)(smem + PS_CS);
    __half* gxs = (__half*)(smem + PS_GX);
    const int tid = threadIdx.x, lane = tid & 31, wid = tid >> 5;
    const int wm = wid >> 1, wn = wid & 1;          // 4(m) x 2(n) warps
    const int n0 = blockIdx.x * 64;
    const int b0 = blockIdx.y * 64;
    const unsigned NCTA = gridDim.x * gridDim.y;    // 128

    const uint32_t aoff = a_lane_off(lane);
    const uint32_t boff = b_lane_off(lane);

    // Resident B: W_h tile 64(n) x 512(k), 8 chunks, loaded once.
#pragma unroll
    for (int c = 0; c < 8; c++) {
#pragma unroll
        for (int q = 0; q < 2; q++) {
            int i = tid + q * 256, r = i >> 3, g = i & 7;
            cp16(sb + PS_B + c * CHUNK_BYTES + r * RSTRIDE + g * 16,
                 g_Whh + (size_t)(n0 + r) * Hh + c * 64 + g * 8);
        }
    }
    CP_COMMIT();

    // Epilogue mapping: thread -> (batch row, quarter of 16-j tile); c in regs.
    const int erow = tid >> 2, ejq = tid & 3;       // 64 rows x 4 j-quads
    const int eb = b0 + erow;
    float cv[4] = {0.0f, 0.0f, 0.0f, 0.0f};

    CP_WAIT(0);
    __syncthreads();

    // Per-warp compute over one 64x64 chunk pair: warp tile 16(m) x 32(n).
    auto compute = [&](int kc, float (&acc)[4][4]) {
        const uint32_t Ab = sb + PS_A + kc * CHUNK_BYTES + (wm * 16) * RSTRIDE;
        const uint32_t Bx = sb + PS_B + kc * CHUNK_BYTES + (wn * 32) * RSTRIDE;
#pragma unroll
        for (int kb = 0; kb < 64; kb += 16) {
            uint32_t a[4], b[2][4];
            ldm_x4(a, Ab + kb * 2 + aoff);
#pragma unroll
            for (int bi = 0; bi < 2; bi++)
                ldm_x4(b[bi], Bx + bi * 16 * RSTRIDE + kb * 2 + boff);
#pragma unroll
            for (int ni = 0; ni < 4; ni++)
                mma16816(acc[ni], a, &b[ni >> 1][(ni & 1) * 2]);
        }
    };

    // h-chunk loader: one 64x64-half chunk, 512 cp16 over 256 threads
    auto load_hchunk = [&](const __half* hin, int c) {
#pragma unroll
        for (int q = 0; q < 2; q++) {
            int i = tid + q * 256, r = i >> 3, g = i & 7;
            cp16(sb + PS_A + c * CHUNK_BYTES + r * RSTRIDE + g * 16,
                 hin + (size_t)(b0 + r) * Hh + c * 64 + g * 8);
        }
    };

    for (int t = 0; t < Tt; t++) {
        const __half* __restrict__ hin  = g_hh[t & 1];
        __half* __restrict__ hout       = g_hh[(t + 1) & 1];

        // 4 commit groups: {gx, h0, h1}, {h2, h3}, {h4, h5}, {h6, h7}
        {
            const __half* gsrc = g_gx + ((size_t)t * Bb + b0) * G4 + n0;
#pragma unroll
            for (int q = 0; q < 2; q++) {
                int i = tid + q * 256, r = i >> 3, g = i & 7;
                cp16(sb + PS_GX + r * 128 + g * 16, gsrc + (size_t)r * G4 + g * 8);
            }
            load_hchunk(hin, 0); load_hchunk(hin, 1); CP_COMMIT();
            load_hchunk(hin, 2); load_hchunk(hin, 3); CP_COMMIT();
            load_hchunk(hin, 4); load_hchunk(hin, 5); CP_COMMIT();
            load_hchunk(hin, 6); load_hchunk(hin, 7); CP_COMMIT();
        }

        float acc[4][4] = {};
        CP_WAIT(3); __syncthreads();
        compute(0, acc); compute(1, acc);
        CP_WAIT(2); __syncthreads();
        compute(2, acc); compute(3, acc);
        CP_WAIT(1); __syncthreads();
        compute(4, acc); compute(5, acc);
        CP_WAIT(0); __syncthreads();
        compute(6, acc); compute(7, acc);

        // Exchange accumulators through smem (row-major Cs[64][68])
        const int r0 = wm * 16 + (lane >> 2);
        const int c0 = wn * 32 + 2 * (lane & 3);
#pragma unroll
        for (int ni = 0; ni < 4; ni++) {
            const int cc = c0 + ni * 8;
            Cs[r0 * CS_STRIDE + cc]           = acc[ni][0];
            Cs[r0 * CS_STRIDE + cc + 1]       = acc[ni][1];
            Cs[(r0 + 8) * CS_STRIDE + cc]     = acc[ni][2];
            Cs[(r0 + 8) * CS_STRIDE + cc + 1] = acc[ni][3];
        }
        __syncthreads();

        // Pointwise LSTM update: 4 j's (16 gate pre-acts) per thread
        {
            const float*  cs = Cs  + erow * CS_STRIDE + ejq * 16;
            const __half* gr = gxs + erow * 64        + ejq * 16;
            __half hb[4];
#pragma unroll
            for (int j = 0; j < 4; j++) {
                float4 pre = *(const float4*)(cs + j * 4);      // W_h·h partial (f,i,c,o)
                float2 g01 = __half22float2(*(const __half2*)(gr + j * 4));
                float2 g23 = __half22float2(*(const __half2*)(gr + j * 4 + 2));
                float fg = sigf(pre.x + g01.x);
                float ig = sigf(pre.y + g01.y);
                float gg = tanhf_(pre.z + g23.x);
                float og = sigf(pre.w + g23.y);
                float cn = fg * cv[j] + ig * gg;
                cv[j] = cn;
                hb[j] = __float2half_rn(og * tanhf_(cn));
            }
            *(uint2*)(hout + (size_t)eb * Hh + (n0 >> 2) + ejq * 4) = *(uint2*)hb;
        }

        // Grid barrier: h(t+1) visible to all before next step
        __threadfence();
        __syncthreads();
        if (tid == 0) {
            atomicAdd(&g_ctr, 1u);
            const unsigned target = (unsigned)(t + 1) * NCTA;
            while (*(volatile unsigned*)&g_ctr < target) __nanosleep(64);
        }
        __syncthreads();
    }
}

// ---------------------------------------------------------------------------
// Output head: logits = h_last @ Wout + bout; log_softmax per row.
// ---------------------------------------------------------------------------
__global__ __launch_bounds__(256) void final_head(
    const float* __restrict__ Wout, const float* __restrict__ bout,
    float* __restrict__ out)
{
    __shared__ float hs[Hh];
    __shared__ float red[256];

    const int b = blockIdx.x;
    const int o = threadIdx.x;
    const __half* hrow = g_hh[0] + (size_t)b * Hh;   // t=511 wrote buffer 0

    for (int k = o; k < Hh; k += 256) hs[k] = __half2float(hrow[k]);
    __syncthreads();

    float acc = bout[o];
#pragma unroll 4
    for (int k = 0; k < Hh; k++)
        acc += hs[k] * Wout[(size_t)k * Oo + o];

    red[o] = acc;
    __syncthreads();
    for (int s = 128; s > 0; s >>= 1) {
        if (o < s) red[o] = fmaxf(red[o], red[o + s]);
        __syncthreads();
    }
    const float mx = red[0];
    __syncthreads();

    red[o] = expf(acc - mx);
    __syncthreads();
    for (int s = 128; s > 0; s >>= 1) {
        if (o < s) red[o] += red[o + s];
        __syncthreads();
    }
    const float lse = logf(red[0]) + mx;
    out[(size_t)b * Oo + o] = acc - lse;
}

// ---------------------------------------------------------------------------
// kernel_launch
// ---------------------------------------------------------------------------
extern "C" void kernel_launch(void* const* d_in, const int* in_sizes, int n_in,
                              void* d_out, int out_size)
{
    const float* inputs = (const float*)d_in[0];
    const float* Wf = (const float*)d_in[1];
    const float* bf = (const float*)d_in[2];
    const float* Wi = (const float*)d_in[3];
    const float* bi = (const float*)d_in[4];
    const float* Wc = (const float*)d_in[5];
    const float* bc = (const float*)d_in[6];
    const float* Wo = (const float*)d_in[7];
    const float* bo = (const float*)d_in[8];
    const float* Wout = (const float*)d_in[9];
    const float* bout = (const float*)d_in[10];
    float* out = (float*)d_out;

    static bool attr_done = false;
    if (!attr_done) {
        cudaFuncSetAttribute(phase1_mma, cudaFuncAttributeMaxDynamicSharedMemorySize, P1_SMEM);
        cudaFuncSetAttribute(lstm_persistent, cudaFuncAttributeMaxDynamicSharedMemorySize, PS_SMEM);
        attr_done = true;
    }

    pack_x<<<(unsigned)((size_t)Tt * Bb * Ii / 4 / 256), 256>>>(inputs);
    pack_w<<<Ii + Hh, 256>>>(Wf, bf, Wi, bi, Wc, bc, Wo, bo);
    zero_state<<<(Bb * Hh + 255) / 256, 256>>>();

    // Phase 1: M = 131072, N = 2048, K = 256
    phase1_mma<<<dim3(G4 / 128, (Tt * Bb) / 64), 256, P1_SMEM>>>();

    // Persistent recurrence: 32 n-tiles x 4 b-tiles = 128 CTAs, single wave
    lstm_persistent<<<dim3(G4 / 64, Bb / 64), 256, PS_SMEM>>>();

    final_head<<<Bb, 256>>>(Wout, bout, out);
}

// round 6
// speedup vs baseline: 1.0570x; 1.0570x over previous
#include <cuda_runtime.h>
#include <cuda_fp16.h>
#include <math.h>
#include <stdint.h>

// Problem constants
constexpr int Bb = 256;    // batch
constexpr int Tt = 512;    // seq len
constexpr int Ii = 256;    // input size
constexpr int Hh = 512;    // hidden size
constexpr int Oo = 256;    // output size
constexpr int G4 = 4 * Hh; // 2048 packed gate width, n = j*4 + g (0=f,1=i,2=c,3=o)

// ---------------------------------------------------------------------------
// Device scratch
// ---------------------------------------------------------------------------
__device__ __half g_gx[(size_t)Tt * Bb * G4];   // 512 MB: input projections fp16, m = t*B+b
__device__ __half g_xh[(size_t)Tt * Bb * Ii];   // 64 MB: x fp16, [m][k]
__device__ __half g_Wxh[(size_t)G4 * Ii];       // W_x packed [n][k] fp16
__device__ __half g_Whh[(size_t)G4 * Hh];       // W_h packed [n][k] fp16
__device__ float  g_biasp[G4];                  // bias packed [n]
__device__ __half g_hh[2][Bb * Hh];             // double-buffered hidden (fp16)
__device__ unsigned g_ctrs[4];                  // per-b-group barrier counters

// ---------------------------------------------------------------------------
// PTX helpers (base PTX only: valid at compute_103 virtual arch)
// ---------------------------------------------------------------------------
__device__ __forceinline__ uint32_t smem_u32(const void* p) {
    uint32_t a;
    asm("{ .reg .u64 t; cvta.to.shared.u64 t, %1; cvt.u32.u64 %0, t; }" : "=r"(a) : "l"(p));
    return a;
}
__device__ __forceinline__ void cp16(uint32_t dst, const void* src) {
    asm volatile("cp.async.cg.shared.global [%0], [%1], 16;" :: "r"(dst), "l"(src));
}
#define CP_COMMIT() asm volatile("cp.async.commit_group;" ::: "memory")
#define CP_WAIT(n)  asm volatile("cp.async.wait_group %0;" :: "n"(n) : "memory")

__device__ __forceinline__ void ldm_x4(uint32_t (&r)[4], uint32_t addr) {
    asm volatile("ldmatrix.sync.aligned.m8n8.x4.shared.b16 {%0,%1,%2,%3}, [%4];"
        : "=r"(r[0]), "=r"(r[1]), "=r"(r[2]), "=r"(r[3]) : "r"(addr));
}
__device__ __forceinline__ void mma16816(float (&c)[4], const uint32_t (&a)[4], const uint32_t* b) {
    asm volatile("mma.sync.aligned.m16n8k16.row.col.f32.f16.f16.f32 "
        "{%0,%1,%2,%3}, {%4,%5,%6,%7}, {%8,%9}, {%0,%1,%2,%3};"
        : "+f"(c[0]), "+f"(c[1]), "+f"(c[2]), "+f"(c[3])
        : "r"(a[0]), "r"(a[1]), "r"(a[2]), "r"(a[3]), "r"(b[0]), "r"(b[1]));
}

// Fast activations (err ~1e-7, below fp16 noise)
__device__ __forceinline__ float ex2f(float x) { float y; asm("ex2.approx.f32 %0, %1;" : "=f"(y) : "f"(x)); return y; }
__device__ __forceinline__ float rcpf(float x) { float y; asm("rcp.approx.f32 %0, %1;" : "=f"(y) : "f"(x)); return y; }
__device__ __forceinline__ float sigf(float x)   { return rcpf(1.0f + ex2f(-1.4426950408889634f * x)); }
__device__ __forceinline__ float tanhf_(float x) { return __fmaf_rn(2.0f, sigf(2.0f * x), -1.0f); }

// SMEM tile geometry: 64 data halves + 8 pad per row -> conflict-free ldmatrix
constexpr int RSTRIDE = 144;                 // bytes per smem row
constexpr int CHUNK_BYTES = 64 * RSTRIDE;    // one 64x64-half chunk = 9216 B

__device__ __forceinline__ uint32_t a_lane_off(int lane) {
    return (uint32_t)(((lane & 7) + ((lane >> 3) & 1) * 8) * RSTRIDE + (lane >> 4) * 16);
}
__device__ __forceinline__ uint32_t b_lane_off(int lane) {
    return (uint32_t)(((lane & 7) + ((lane >> 4) & 1) * 8) * RSTRIDE + ((lane >> 3) & 1) * 16);
}

// ---------------------------------------------------------------------------
// Packing
// ---------------------------------------------------------------------------
__global__ void pack_x(const float* __restrict__ x) {
    size_t e = ((size_t)blockIdx.x * blockDim.x + threadIdx.x) * 4;
    if (e >= (size_t)Tt * Bb * Ii) return;
    int    k  = (int)(e & 255);
    size_t md = e >> 8;
    int    b  = (int)(md & 255);
    int    t  = (int)(md >> 8);
    float4 v = *(const float4*)(x + ((size_t)b * Tt + t) * Ii + k);
    *(__half2*)(g_xh + e)     = __floats2half2_rn(v.x, v.y);
    *(__half2*)(g_xh + e + 2) = __floats2half2_rn(v.z, v.w);
}

__global__ void pack_w(const float* __restrict__ Wf, const float* __restrict__ bf,
                       const float* __restrict__ Wi, const float* __restrict__ bi,
                       const float* __restrict__ Wc, const float* __restrict__ bc,
                       const float* __restrict__ Wo, const float* __restrict__ bo) {
    int k = blockIdx.x;  // 0..767
    for (int n = threadIdx.x; n < G4; n += blockDim.x) {
        int g = n & 3, j = n >> 2;
        const float* W = (g == 0) ? Wf : (g == 1) ? Wi : (g == 2) ? Wc : Wo;
        float v = W[(size_t)k * Hh + j];
        if (k < Ii) g_Wxh[(size_t)n * Ii + k] = __float2half_rn(v);
        else        g_Whh[(size_t)n * Hh + (k - Ii)] = __float2half_rn(v);
        if (k == 0) {
            const float* bp = (g == 0) ? bf : (g == 1) ? bi : (g == 2) ? bc : bo;
            g_biasp[n] = bp[j];
        }
    }
}

__global__ void zero_state() {
    int i = blockIdx.x * blockDim.x + threadIdx.x;
    if (i < 4) g_ctrs[i] = 0;
    if (i < Bb * Hh) g_hh[0][i] = __float2half_rn(0.0f);
}

// ---------------------------------------------------------------------------
// Phase 1: gx[m][n] = fp16( sum_k xh[m][k] * Wxh[n][k] + bias[n] )
//   CTA 64(M) x 128(N), 256 thr (8 warps = 2x4), K=256 in 4 cp.async stages.
// ---------------------------------------------------------------------------
constexpr uint32_t P1_A0 = 0,      P1_B0 = 9216;
constexpr uint32_t P1_A1 = 27648,  P1_B1 = 36864;
constexpr int P1_SMEM = 55296;

__global__ void __launch_bounds__(256) phase1_mma() {
    extern __shared__ __align__(128) char smem[];
    const uint32_t sb = smem_u32(smem);
    const int tid = threadIdx.x, lane = tid & 31, wid = tid >> 5;
    const int wm = wid >> 2, wn = wid & 3;
    const int n0 = blockIdx.x * 128;
    const int m0 = blockIdx.y * 64;

    const uint32_t aoff = a_lane_off(lane);
    const uint32_t boff = b_lane_off(lane);

    float acc[2][4][4] = {};

    auto load_stage = [&](int s, uint32_t Ab, uint32_t Bx) {
        const int kb0 = s * 64;
#pragma unroll
        for (int q = 0; q < 2; q++) {
            int i = tid + q * 256, r = i >> 3, g = i & 7;
            cp16(sb + Ab + r * RSTRIDE + g * 16, g_xh + (size_t)(m0 + r) * Ii + kb0 + g * 8);
        }
#pragma unroll
        for (int q = 0; q < 4; q++) {
            int i = tid + q * 256, r = i >> 3, g = i & 7;
            cp16(sb + Bx + r * RSTRIDE + g * 16, g_Wxh + (size_t)(n0 + r) * Ii + kb0 + g * 8);
        }
        CP_COMMIT();
    };
    auto compute = [&](uint32_t Ab, uint32_t Bx) {
#pragma unroll
        for (int kb = 0; kb < 64; kb += 16) {
            uint32_t a[2][4], b[2][4];
#pragma unroll
            for (int mi = 0; mi < 2; mi++)
                ldm_x4(a[mi], sb + Ab + (wm * 32 + mi * 16) * RSTRIDE + kb * 2 + aoff);
#pragma unroll
            for (int bi = 0; bi < 2; bi++)
                ldm_x4(b[bi], sb + Bx + (wn * 32 + bi * 16) * RSTRIDE + kb * 2 + boff);
#pragma unroll
            for (int mi = 0; mi < 2; mi++)
#pragma unroll
                for (int ni = 0; ni < 4; ni++)
                    mma16816(acc[mi][ni], a[mi], &b[ni >> 1][(ni & 1) * 2]);
        }
    };

    load_stage(0, P1_A0, P1_B0);
#pragma unroll
    for (int s = 0; s < 4; s++) {
        if (s < 3) { load_stage(s + 1, (s & 1) ? P1_A0 : P1_A1, (s & 1) ? P1_B0 : P1_B1); CP_WAIT(1); }
        else       { CP_WAIT(0); }
        __syncthreads();
        compute((s & 1) ? P1_A1 : P1_A0, (s & 1) ? P1_B1 : P1_B0);
        __syncthreads();
    }

    // Epilogue: fp16 store with bias
    const int r0 = wm * 32 + (lane >> 2);
    const int c0 = wn * 32 + 2 * (lane & 3);
#pragma unroll
    for (int mi = 0; mi < 2; mi++) {
#pragma unroll
        for (int ni = 0; ni < 4; ni++) {
            const int n = n0 + c0 + ni * 8;
            const float2 bv = *(const float2*)&g_biasp[n];
            const int m = m0 + r0 + mi * 16;
            *(__half2*)(g_gx + (size_t)m * G4 + n) =
                __floats2half2_rn(acc[mi][ni][0] + bv.x, acc[mi][ni][1] + bv.y);
            *(__half2*)(g_gx + (size_t)(m + 8) * G4 + n) =
                __floats2half2_rn(acc[mi][ni][2] + bv.x, acc[mi][ni][3] + bv.y);
        }
    }
}

// ---------------------------------------------------------------------------
// Persistent recurrence: 128 CTAs (32 n-tiles x 4 b-tiles), all 512 steps.
// 128 threads (4 warps, 2m x 2n, 32x32 warp tiles). W_h resident in smem;
// c in registers; gx double-buffer prefetched one step ahead; per-b-group
// spin barrier (fan-in 32) with release/acquire atomics, no sleep.
// ---------------------------------------------------------------------------
constexpr uint32_t PS_A  = 0;                       // A (h) chunks: 8 x 9216
constexpr uint32_t PS_B  = 8 * CHUNK_BYTES;         // B (Wh) resident: 8 x 9216
constexpr uint32_t PS_GX = 16 * CHUNK_BYTES;        // gx double buffer: 2 x 8192
constexpr uint32_t PS_CS = PS_GX + 16384;           // Cs exchange: 64 x 68 f32
constexpr int CS_STRIDE = 68;
constexpr int PS_SMEM = PS_CS + 64 * CS_STRIDE * 4; // 181248 B

__global__ void __launch_bounds__(128) lstm_persistent() {
    extern __shared__ __align__(128) char smem[];
    const uint32_t sb = smem_u32(smem);
    float*  Cs  = (float*)(smem + PS_CS);
    __half* gxs = (__half*)(smem + PS_GX);
    const int tid = threadIdx.x, lane = tid & 31, wid = tid >> 5;
    const int wm = wid >> 1, wn = wid & 1;
    const int n0 = blockIdx.x * 64;
    const int b0 = blockIdx.y * 64;
    unsigned* const ctr = &g_ctrs[blockIdx.y];      // per-b-group barrier, fan-in 32

    const uint32_t aoff = a_lane_off(lane);
    const uint32_t boff = b_lane_off(lane);

    // Resident B: W_h tile 64(n) x 512(k), 8 chunks, loaded once.
#pragma unroll
    for (int c = 0; c < 8; c++) {
#pragma unroll
        for (int q = 0; q < 4; q++) {
            int i = tid + q * 128, r = i >> 3, g = i & 7;
            cp16(sb + PS_B + c * CHUNK_BYTES + r * RSTRIDE + g * 16,
                 g_Whh + (size_t)(n0 + r) * Hh + c * 64 + g * 8);
        }
    }
    // Preload gx(0) into buffer 0
    {
        const __half* gsrc = g_gx + (size_t)b0 * G4 + n0;
#pragma unroll
        for (int q = 0; q < 4; q++) {
            int i = tid + q * 128, r = i >> 3, g = i & 7;
            cp16(sb + PS_GX + r * 128 + g * 16, gsrc + (size_t)r * G4 + g * 8);
        }
    }
    CP_COMMIT();

    // Epilogue mapping: thread -> (batch row, half of 16-j tile); c in regs.
    const int erow = tid >> 1, ejq = tid & 1;
    const int eb = b0 + erow;
    float cv[8];
#pragma unroll
    for (int j = 0; j < 8; j++) cv[j] = 0.0f;

    CP_WAIT(0);
    __syncthreads();

    auto compute = [&](int kc, float (&acc)[2][4][4]) {
        const uint32_t Ab = sb + PS_A + kc * CHUNK_BYTES;
        const uint32_t Bx = sb + PS_B + kc * CHUNK_BYTES;
#pragma unroll
        for (int kb = 0; kb < 64; kb += 16) {
            uint32_t a[2][4], b[2][4];
#pragma unroll
            for (int mi = 0; mi < 2; mi++)
                ldm_x4(a[mi], Ab + (wm * 32 + mi * 16) * RSTRIDE + kb * 2 + aoff);
#pragma unroll
            for (int bi = 0; bi < 2; bi++)
                ldm_x4(b[bi], Bx + (wn * 32 + bi * 16) * RSTRIDE + kb * 2 + boff);
#pragma unroll
            for (int mi = 0; mi < 2; mi++)
#pragma unroll
                for (int ni = 0; ni < 4; ni++)
                    mma16816(acc[mi][ni], a[mi], &b[ni >> 1][(ni & 1) * 2]);
        }
    };
    auto load_hchunk = [&](const __half* hin, int c) {
#pragma unroll
        for (int q = 0; q < 4; q++) {
            int i = tid + q * 128, r = i >> 3, g = i & 7;
            cp16(sb + PS_A + c * CHUNK_BYTES + r * RSTRIDE + g * 16,
                 hin + (size_t)(b0 + r) * Hh + c * 64 + g * 8);
        }
    };

    for (int t = 0; t < Tt; t++) {
        const __half* __restrict__ hin  = g_hh[t & 1];
        __half* __restrict__ hout       = g_hh[(t + 1) & 1];

        // Group 1: h chunks 0..3 ; Group 2: h chunks 4..7
        load_hchunk(hin, 0); load_hchunk(hin, 1);
        load_hchunk(hin, 2); load_hchunk(hin, 3); CP_COMMIT();
        load_hchunk(hin, 4); load_hchunk(hin, 5);
        load_hchunk(hin, 6); load_hchunk(hin, 7); CP_COMMIT();
        // Group 3: prefetch gx(t+1) into alternate buffer (independent of barrier)
        if (t + 1 < Tt) {
            const __half* gsrc = g_gx + ((size_t)(t + 1) * Bb + b0) * G4 + n0;
            const uint32_t gdst = sb + PS_GX + ((t + 1) & 1) * 8192;
#pragma unroll
            for (int q = 0; q < 4; q++) {
                int i = tid + q * 128, r = i >> 3, g = i & 7;
                cp16(gdst + r * 128 + g * 16, gsrc + (size_t)r * G4 + g * 8);
            }
        }
        CP_COMMIT();

        float acc[2][4][4] = {};
        CP_WAIT(2);             // group 1 done (and last step's gx prefetch)
        __syncthreads();
        compute(0, acc); compute(1, acc); compute(2, acc); compute(3, acc);
        CP_WAIT(1);             // group 2 done
        __syncthreads();
        compute(4, acc); compute(5, acc); compute(6, acc); compute(7, acc);

        // Exchange accumulators through smem (row-major Cs)
        const int r0 = wm * 32 + (lane >> 2);
        const int c0 = wn * 32 + 2 * (lane & 3);
#pragma unroll
        for (int mi = 0; mi < 2; mi++) {
#pragma unroll
            for (int ni = 0; ni < 4; ni++) {
                const int rr = r0 + mi * 16, cc = c0 + ni * 8;
                Cs[rr * CS_STRIDE + cc]           = acc[mi][ni][0];
                Cs[rr * CS_STRIDE + cc + 1]       = acc[mi][ni][1];
                Cs[(rr + 8) * CS_STRIDE + cc]     = acc[mi][ni][2];
                Cs[(rr + 8) * CS_STRIDE + cc + 1] = acc[mi][ni][3];
            }
        }
        __syncthreads();

        // Pointwise LSTM update (c in registers); gx from this step's buffer
        {
            const float*  cs = Cs + erow * CS_STRIDE + ejq * 32;
            const __half* gr = gxs + (t & 1) * 4096 + erow * 64 + ejq * 32;
            __half hb[8];
#pragma unroll
            for (int j = 0; j < 8; j++) {
                float4 pre = *(const float4*)(cs + j * 4);      // W_h·h partial (f,i,c,o)
                float2 g01 = __half22float2(*(const __half2*)(gr + j * 4));
                float2 g23 = __half22float2(*(const __half2*)(gr + j * 4 + 2));
                float fg = sigf(pre.x + g01.x);
                float ig = sigf(pre.y + g01.y);
                float gg = tanhf_(pre.z + g23.x);
                float og = sigf(pre.w + g23.y);
                float cn = fg * cv[j] + ig * gg;
                cv[j] = cn;
                hb[j] = __float2half_rn(og * tanhf_(cn));
            }
            *(uint4*)(hout + (size_t)eb * Hh + (n0 >> 2) + ejq * 8) = *(uint4*)hb;
        }

        // Per-b-group barrier: release h(t+1), tight acquire spin (no sleep)
        __threadfence();
        __syncthreads();
        if (tid == 0) {
            asm volatile("red.release.gpu.global.add.u32 [%0], %1;"
                         :: "l"(ctr), "r"(1u) : "memory");
            const unsigned target = (unsigned)(t + 1) * 32u;
            unsigned v;
            do {
                asm volatile("ld.acquire.gpu.global.u32 %0, [%1];"
                             : "=r"(v) : "l"(ctr) : "memory");
            } while (v < target);
        }
        __syncthreads();
    }
}

// ---------------------------------------------------------------------------
// Output head: logits = h_last @ Wout + bout; log_softmax per row.
// ---------------------------------------------------------------------------
__global__ __launch_bounds__(256) void final_head(
    const float* __restrict__ Wout, const float* __restrict__ bout,
    float* __restrict__ out)
{
    __shared__ float hs[Hh];
    __shared__ float red[256];

    const int b = blockIdx.x;
    const int o = threadIdx.x;
    const __half* hrow = g_hh[0] + (size_t)b * Hh;   // t=511 wrote buffer 0

    for (int k = o; k < Hh; k += 256) hs[k] = __half2float(hrow[k]);
    __syncthreads();

    float acc = bout[o];
#pragma unroll 4
    for (int k = 0; k < Hh; k++)
        acc += hs[k] * Wout[(size_t)k * Oo + o];

    red[o] = acc;
    __syncthreads();
    for (int s = 128; s > 0; s >>= 1) {
        if (o < s) red[o] = fmaxf(red[o], red[o + s]);
        __syncthreads();
    }
    const float mx = red[0];
    __syncthreads();

    red[o] = expf(acc - mx);
    __syncthreads();
    for (int s = 128; s > 0; s >>= 1) {
        if (o < s) red[o] += red[o + s];
        __syncthreads();
    }
    const float lse = logf(red[0]) + mx;
    out[(size_t)b * Oo + o] = acc - lse;
}

// ---------------------------------------------------------------------------
// kernel_launch
// ---------------------------------------------------------------------------
extern "C" void kernel_launch(void* const* d_in, const int* in_sizes, int n_in,
                              void* d_out, int out_size)
{
    const float* inputs = (const float*)d_in[0];
    const float* Wf = (const float*)d_in[1];
    const float* bf = (const float*)d_in[2];
    const float* Wi = (const float*)d_in[3];
    const float* bi = (const float*)d_in[4];
    const float* Wc = (const float*)d_in[5];
    const float* bc = (const float*)d_in[6];
    const float* Wo = (const float*)d_in[7];
    const float* bo = (const float*)d_in[8];
    const float* Wout = (const float*)d_in[9];
    const float* bout = (const float*)d_in[10];
    float* out = (float*)d_out;

    static bool attr_done = false;
    if (!attr_done) {
        cudaFuncSetAttribute(phase1_mma, cudaFuncAttributeMaxDynamicSharedMemorySize, P1_SMEM);
        cudaFuncSetAttribute(lstm_persistent, cudaFuncAttributeMaxDynamicSharedMemorySize, PS_SMEM);
        attr_done = true;
    }

    pack_x<<<(unsigned)((size_t)Tt * Bb * Ii / 4 / 256), 256>>>(inputs);
    pack_w<<<Ii + Hh, 256>>>(Wf, bf, Wi, bi, Wc, bc, Wo, bo);
    zero_state<<<(Bb * Hh + 255) / 256, 256>>>();

    // Phase 1: M = 131072, N = 2048, K = 256
    phase1_mma<<<dim3(G4 / 128, (Tt * Bb) / 64), 256, P1_SMEM>>>();

    // Persistent recurrence: 32 n-tiles x 4 b-tiles = 128 CTAs, single wave
    lstm_persistent<<<dim3(G4 / 64, Bb / 64), 128, PS_SMEM>>>();

    final_head<<<Bb, 256>>>(Wout, bout, out);
}

// round 7
// speedup vs baseline: 1.1244x; 1.0638x over previous
#include <cuda_runtime.h>
#include <cuda_fp16.h>
#include <math.h>
#include <stdint.h>

// Problem constants
constexpr int Bb = 256;    // batch
constexpr int Tt = 512;    // seq len
constexpr int Ii = 256;    // input size
constexpr int Hh = 512;    // hidden size
constexpr int Oo = 256;    // output size
constexpr int G4 = 4 * Hh; // 2048 packed gate width, n = j*4 + g (0=f,1=i,2=c,3=o)

// ---------------------------------------------------------------------------
// Device scratch
// ---------------------------------------------------------------------------
__device__ __half g_gx[(size_t)Tt * Bb * G4];   // 512 MB: input projections fp16, m = t*B+b
__device__ __half g_xh[(size_t)Tt * Bb * Ii];   // 64 MB: x fp16, [m][k]
__device__ __half g_Wxh[(size_t)G4 * Ii];       // W_x packed [n][k] fp16
__device__ __half g_Whh[(size_t)G4 * Hh];       // W_h packed [n][k] fp16
__device__ float  g_biasp[G4];                  // bias packed [n]
__device__ __half g_hh[2][Bb * Hh];             // double-buffered hidden (fp16)
__device__ unsigned g_ctrs[8];                  // per-b-group barrier counters

// ---------------------------------------------------------------------------
// PTX helpers (base PTX only: valid at compute_103 virtual arch)
// ---------------------------------------------------------------------------
__device__ __forceinline__ uint32_t smem_u32(const void* p) {
    uint32_t a;
    asm("{ .reg .u64 t; cvta.to.shared.u64 t, %1; cvt.u32.u64 %0, t; }" : "=r"(a) : "l"(p));
    return a;
}
__device__ __forceinline__ void cp16(uint32_t dst, const void* src) {
    asm volatile("cp.async.cg.shared.global [%0], [%1], 16;" :: "r"(dst), "l"(src));
}
#define CP_COMMIT() asm volatile("cp.async.commit_group;" ::: "memory")
#define CP_WAIT(n)  asm volatile("cp.async.wait_group %0;" :: "n"(n) : "memory")

__device__ __forceinline__ void ldm_x4(uint32_t (&r)[4], uint32_t addr) {
    asm volatile("ldmatrix.sync.aligned.m8n8.x4.shared.b16 {%0,%1,%2,%3}, [%4];"
        : "=r"(r[0]), "=r"(r[1]), "=r"(r[2]), "=r"(r[3]) : "r"(addr));
}
__device__ __forceinline__ void mma16816(float (&c)[4], const uint32_t (&a)[4], const uint32_t* b) {
    asm volatile("mma.sync.aligned.m16n8k16.row.col.f32.f16.f16.f32 "
        "{%0,%1,%2,%3}, {%4,%5,%6,%7}, {%8,%9}, {%0,%1,%2,%3};"
        : "+f"(c[0]), "+f"(c[1]), "+f"(c[2]), "+f"(c[3])
        : "r"(a[0]), "r"(a[1]), "r"(a[2]), "r"(a[3]), "r"(b[0]), "r"(b[1]));
}

// Fast activations (err ~1e-7, below fp16 noise)
__device__ __forceinline__ float ex2f(float x) { float y; asm("ex2.approx.f32 %0, %1;" : "=f"(y) : "f"(x)); return y; }
__device__ __forceinline__ float rcpf(float x) { float y; asm("rcp.approx.f32 %0, %1;" : "=f"(y) : "f"(x)); return y; }
__device__ __forceinline__ float sigf(float x)   { return rcpf(1.0f + ex2f(-1.4426950408889634f * x)); }
__device__ __forceinline__ float tanhf_(float x) { return __fmaf_rn(2.0f, sigf(2.0f * x), -1.0f); }

// SMEM tile geometry: 64 data halves + 8 pad per row -> conflict-free ldmatrix
constexpr int RSTRIDE = 144;   // bytes per smem row

__device__ __forceinline__ uint32_t a_lane_off(int lane) {
    return (uint32_t)(((lane & 7) + ((lane >> 3) & 1) * 8) * RSTRIDE + (lane >> 4) * 16);
}
__device__ __forceinline__ uint32_t b_lane_off(int lane) {
    return (uint32_t)(((lane & 7) + ((lane >> 4) & 1) * 8) * RSTRIDE + ((lane >> 3) & 1) * 16);
}

// ---------------------------------------------------------------------------
// Packing
// ---------------------------------------------------------------------------
__global__ void pack_x(const float* __restrict__ x) {
    size_t e = ((size_t)blockIdx.x * blockDim.x + threadIdx.x) * 4;
    if (e >= (size_t)Tt * Bb * Ii) return;
    int    k  = (int)(e & 255);
    size_t md = e >> 8;
    int    b  = (int)(md & 255);
    int    t  = (int)(md >> 8);
    float4 v = *(const float4*)(x + ((size_t)b * Tt + t) * Ii + k);
    *(__half2*)(g_xh + e)     = __floats2half2_rn(v.x, v.y);
    *(__half2*)(g_xh + e + 2) = __floats2half2_rn(v.z, v.w);
}

__global__ void pack_w(const float* __restrict__ Wf, const float* __restrict__ bf,
                       const float* __restrict__ Wi, const float* __restrict__ bi,
                       const float* __restrict__ Wc, const float* __restrict__ bc,
                       const float* __restrict__ Wo, const float* __restrict__ bo) {
    int k = blockIdx.x;  // 0..767
    for (int n = threadIdx.x; n < G4; n += blockDim.x) {
        int g = n & 3, j = n >> 2;
        const float* W = (g == 0) ? Wf : (g == 1) ? Wi : (g == 2) ? Wc : Wo;
        float v = W[(size_t)k * Hh + j];
        if (k < Ii) g_Wxh[(size_t)n * Ii + k] = __float2half_rn(v);
        else        g_Whh[(size_t)n * Hh + (k - Ii)] = __float2half_rn(v);
        if (k == 0) {
            const float* bp = (g == 0) ? bf : (g == 1) ? bi : (g == 2) ? bc : bo;
            g_biasp[n] = bp[j];
        }
    }
}

__global__ void zero_state() {
    int i = blockIdx.x * blockDim.x + threadIdx.x;
    if (i < 8) g_ctrs[i] = 0;
    if (i < Bb * Hh) g_hh[0][i] = __float2half_rn(0.0f);
}

// ---------------------------------------------------------------------------
// Phase 1: gx[m][n] = fp16( sum_k xh[m][k] * Wxh[n][k] + bias[n] )
//   CTA 128(M) x 128(N), 256 thr (8 warps = 2m x 4n, 64x32 warp tiles),
//   K=256 in 4 cp.async double-buffered stages.
// ---------------------------------------------------------------------------
constexpr uint32_t P1_A0 = 0,      P1_B0 = 18432;
constexpr uint32_t P1_A1 = 36864,  P1_B1 = 55296;
constexpr int P1_SMEM = 73728;

__global__ void __launch_bounds__(256) phase1_mma() {
    extern __shared__ __align__(128) char smem[];
    const uint32_t sb = smem_u32(smem);
    const int tid = threadIdx.x, lane = tid & 31, wid = tid >> 5;
    const int wm = wid >> 2, wn = wid & 3;
    const int n0 = blockIdx.x * 128;
    const int m0 = blockIdx.y * 128;

    const uint32_t aoff = a_lane_off(lane);
    const uint32_t boff = b_lane_off(lane);

    float acc[4][4][4] = {};

    auto load_stage = [&](int s, uint32_t Ab, uint32_t Bx) {
        const int kb0 = s * 64;
#pragma unroll
        for (int q = 0; q < 4; q++) {                       // A: 128 x 64h
            int i = tid + q * 256, r = i >> 3, g = i & 7;
            cp16(sb + Ab + r * RSTRIDE + g * 16, g_xh + (size_t)(m0 + r) * Ii + kb0 + g * 8);
        }
#pragma unroll
        for (int q = 0; q < 4; q++) {                       // B: 128 x 64h
            int i = tid + q * 256, r = i >> 3, g = i & 7;
            cp16(sb + Bx + r * RSTRIDE + g * 16, g_Wxh + (size_t)(n0 + r) * Ii + kb0 + g * 8);
        }
        CP_COMMIT();
    };
    auto compute = [&](uint32_t Ab, uint32_t Bx) {
#pragma unroll
        for (int kb = 0; kb < 64; kb += 16) {
            uint32_t a[4][4], b[2][4];
#pragma unroll
            for (int mi = 0; mi < 4; mi++)
                ldm_x4(a[mi], sb + Ab + (wm * 64 + mi * 16) * RSTRIDE + kb * 2 + aoff);
#pragma unroll
            for (int bi = 0; bi < 2; bi++)
                ldm_x4(b[bi], sb + Bx + (wn * 32 + bi * 16) * RSTRIDE + kb * 2 + boff);
#pragma unroll
            for (int mi = 0; mi < 4; mi++)
#pragma unroll
                for (int ni = 0; ni < 4; ni++)
                    mma16816(acc[mi][ni], a[mi], &b[ni >> 1][(ni & 1) * 2]);
        }
    };

    load_stage(0, P1_A0, P1_B0);
#pragma unroll
    for (int s = 0; s < 4; s++) {
        if (s < 3) { load_stage(s + 1, (s & 1) ? P1_A0 : P1_A1, (s & 1) ? P1_B0 : P1_B1); CP_WAIT(1); }
        else       { CP_WAIT(0); }
        __syncthreads();
        compute((s & 1) ? P1_A1 : P1_A0, (s & 1) ? P1_B1 : P1_B0);
        __syncthreads();
    }

    // Epilogue: fp16 store with bias
    const int r0 = wm * 64 + (lane >> 2);
    const int c0 = wn * 32 + 2 * (lane & 3);
#pragma unroll
    for (int mi = 0; mi < 4; mi++) {
#pragma unroll
        for (int ni = 0; ni < 4; ni++) {
            const int n = n0 + c0 + ni * 8;
            const float2 bv = *(const float2*)&g_biasp[n];
            const int m = m0 + r0 + mi * 16;
            *(__half2*)(g_gx + (size_t)m * G4 + n) =
                __floats2half2_rn(acc[mi][ni][0] + bv.x, acc[mi][ni][1] + bv.y);
            *(__half2*)(g_gx + (size_t)(m + 8) * G4 + n) =
                __floats2half2_rn(acc[mi][ni][2] + bv.x, acc[mi][ni][3] + bv.y);
        }
    }
}

// ---------------------------------------------------------------------------
// Persistent recurrence: 128 CTAs = 16 n-tiles(128) x 8 b-groups(32), all 512
// steps. 128 threads (4 warps = 1m x 4n, 32x32 warp tiles). W_h tile (128KB)
// resident in smem; c in registers; gx prefetched into registers from global;
// per-b-group spin barrier (fan-in 16), release/acquire, no sleep.
// ---------------------------------------------------------------------------
constexpr int A_CHUNK = 32 * RSTRIDE;                 // 4608 B  (32 rows x 64 halves)
constexpr int B_CHUNK = 128 * RSTRIDE;                // 18432 B (128 rows x 64 halves)
constexpr uint32_t PS_A  = 0;                         // A (h) chunks: 8 x 4608 = 36864
constexpr uint32_t PS_B  = 8 * A_CHUNK;               // B (Wh) resident: 8 x 18432 = 147456
constexpr uint32_t PS_CS = PS_B + 8 * B_CHUNK;        // Cs exchange: 32 x 132 f32
constexpr int CS_STRIDE = 132;
constexpr int PS_SMEM = PS_CS + 32 * CS_STRIDE * 4;   // 201216 B

__global__ void __launch_bounds__(128) lstm_persistent() {
    extern __shared__ __align__(128) char smem[];
    const uint32_t sb = smem_u32(smem);
    float* Cs = (float*)(smem + PS_CS);
    const int tid = threadIdx.x, lane = tid & 31, wn = tid >> 5;  // 4 warps along n
    const int n0 = blockIdx.x * 128;
    const int b0 = blockIdx.y * 32;
    unsigned* const ctr = &g_ctrs[blockIdx.y];        // per-b-group barrier, fan-in 16

    const uint32_t aoff = a_lane_off(lane);
    const uint32_t boff = b_lane_off(lane);

    // Resident B: W_h tile 128(n) x 512(k), 8 chunks, loaded once.
#pragma unroll
    for (int c = 0; c < 8; c++) {
#pragma unroll
        for (int q = 0; q < 8; q++) {
            int i = tid + q * 128, r = i >> 3, g = i & 7;
            cp16(sb + PS_B + c * B_CHUNK + r * RSTRIDE + g * 16,
                 g_Whh + (size_t)(n0 + r) * Hh + c * 64 + g * 8);
        }
    }
    CP_COMMIT();

    // Epilogue mapping: thread -> (batch row, 8-j segment); c in regs.
    const int erow = tid >> 2, ejq = tid & 3;         // 32 rows x 4 segs
    const int eb = b0 + erow;
    const int j0 = n0 >> 2;
    float cv[8];
#pragma unroll
    for (int j = 0; j < 8; j++) cv[j] = 0.0f;

    CP_WAIT(0);
    __syncthreads();

    auto compute = [&](int kc, float (&acc)[2][4][4]) {
        const uint32_t Ab = sb + PS_A + kc * A_CHUNK;
        const uint32_t Bx = sb + PS_B + kc * B_CHUNK + (wn * 32) * RSTRIDE;
#pragma unroll
        for (int kb = 0; kb < 64; kb += 16) {
            uint32_t a[2][4], b[2][4];
#pragma unroll
            for (int mi = 0; mi < 2; mi++)
                ldm_x4(a[mi], Ab + mi * 16 * RSTRIDE + kb * 2 + aoff);
#pragma unroll
            for (int bi = 0; bi < 2; bi++)
                ldm_x4(b[bi], Bx + bi * 16 * RSTRIDE + kb * 2 + boff);
#pragma unroll
            for (int mi = 0; mi < 2; mi++)
#pragma unroll
                for (int ni = 0; ni < 4; ni++)
                    mma16816(acc[mi][ni], a[mi], &b[ni >> 1][(ni & 1) * 2]);
        }
    };
    auto load_hchunk = [&](const __half* hin, int c) {
#pragma unroll
        for (int q = 0; q < 2; q++) {
            int i = tid + q * 128, r = i >> 3, g = i & 7;
            cp16(sb + PS_A + c * A_CHUNK + r * RSTRIDE + g * 16,
                 hin + (size_t)(b0 + r) * Hh + c * 64 + g * 8);
        }
    };

    for (int t = 0; t < Tt; t++) {
        const __half* __restrict__ hin  = g_hh[t & 1];
        __half* __restrict__ hout       = g_hh[(t + 1) & 1];

        // gx(t) prefetch into registers (no barrier dependency; ~2us to use)
        uint4 gxp[4];
        {
            const uint4* gsrc = (const uint4*)(g_gx + ((size_t)t * Bb + eb) * G4 + n0 + ejq * 32);
#pragma unroll
            for (int i = 0; i < 4; i++) gxp[i] = gsrc[i];
        }

        // h loads: 2 commit groups of 4 chunks
        load_hchunk(hin, 0); load_hchunk(hin, 1);
        load_hchunk(hin, 2); load_hchunk(hin, 3); CP_COMMIT();
        load_hchunk(hin, 4); load_hchunk(hin, 5);
        load_hchunk(hin, 6); load_hchunk(hin, 7); CP_COMMIT();

        float acc[2][4][4] = {};
        CP_WAIT(1);
        __syncthreads();
        compute(0, acc); compute(1, acc); compute(2, acc); compute(3, acc);
        CP_WAIT(0);
        __syncthreads();
        compute(4, acc); compute(5, acc); compute(6, acc); compute(7, acc);

        // Exchange accumulators through smem (Cs[32][132])
        const int r0 = lane >> 2;
        const int c0 = wn * 32 + 2 * (lane & 3);
#pragma unroll
        for (int mi = 0; mi < 2; mi++) {
#pragma unroll
            for (int ni = 0; ni < 4; ni++) {
                const int rr = r0 + mi * 16, cc = c0 + ni * 8;
                Cs[rr * CS_STRIDE + cc]           = acc[mi][ni][0];
                Cs[rr * CS_STRIDE + cc + 1]       = acc[mi][ni][1];
                Cs[(rr + 8) * CS_STRIDE + cc]     = acc[mi][ni][2];
                Cs[(rr + 8) * CS_STRIDE + cc + 1] = acc[mi][ni][3];
            }
        }
        __syncthreads();

        // Pointwise LSTM update: 8 j's per thread; gx from registers
        {
            const float* cs = Cs + erow * CS_STRIDE + ejq * 32;
            const uint32_t* gxh2 = (const uint32_t*)gxp;   // 8 x (2 halves) pairs
            __half hb[8];
#pragma unroll
            for (int j = 0; j < 8; j++) {
                float4 pre = *(const float4*)(cs + j * 4);           // W_h·h (f,i,c,o)
                float2 g01 = __half22float2(*(const __half2*)&gxh2[j * 2]);
                float2 g23 = __half22float2(*(const __half2*)&gxh2[j * 2 + 1]);
                float fg = sigf(pre.x + g01.x);
                float ig = sigf(pre.y + g01.y);
                float gg = tanhf_(pre.z + g23.x);
                float og = sigf(pre.w + g23.y);
                float cn = fg * cv[j] + ig * gg;
                cv[j] = cn;
                hb[j] = __float2half_rn(og * tanhf_(cn));
            }
            *(uint4*)(hout + (size_t)eb * Hh + j0 + ejq * 8) = *(uint4*)hb;
        }

        // Per-b-group barrier: release h(t+1), tight acquire spin
        __threadfence();
        __syncthreads();
        if (tid == 0) {
            asm volatile("red.release.gpu.global.add.u32 [%0], %1;"
                         :: "l"(ctr), "r"(1u) : "memory");
            const unsigned target = (unsigned)(t + 1) * 16u;
            unsigned v;
            do {
                asm volatile("ld.acquire.gpu.global.u32 %0, [%1];"
                             : "=r"(v) : "l"(ctr) : "memory");
            } while (v < target);
        }
        __syncthreads();
    }
}

// ---------------------------------------------------------------------------
// Output head: logits = h_last @ Wout + bout; log_softmax per row.
// ---------------------------------------------------------------------------
__global__ __launch_bounds__(256) void final_head(
    const float* __restrict__ Wout, const float* __restrict__ bout,
    float* __restrict__ out)
{
    __shared__ float hs[Hh];
    __shared__ float red[256];

    const int b = blockIdx.x;
    const int o = threadIdx.x;
    const __half* hrow = g_hh[0] + (size_t)b * Hh;   // t=511 wrote buffer 0

    for (int k = o; k < Hh; k += 256) hs[k] = __half2float(hrow[k]);
    __syncthreads();

    float acc = bout[o];
#pragma unroll 4
    for (int k = 0; k < Hh; k++)
        acc += hs[k] * Wout[(size_t)k * Oo + o];

    red[o] = acc;
    __syncthreads();
    for (int s = 128; s > 0; s >>= 1) {
        if (o < s) red[o] = fmaxf(red[o], red[o + s]);
        __syncthreads();
    }
    const float mx = red[0];
    __syncthreads();

    red[o] = expf(acc - mx);
    __syncthreads();
    for (int s = 128; s > 0; s >>= 1) {
        if (o < s) red[o] += red[o + s];
        __syncthreads();
    }
    const float lse = logf(red[0]) + mx;
    out[(size_t)b * Oo + o] = acc - lse;
}

// ---------------------------------------------------------------------------
// kernel_launch
// ---------------------------------------------------------------------------
extern "C" void kernel_launch(void* const* d_in, const int* in_sizes, int n_in,
                              void* d_out, int out_size)
{
    const float* inputs = (const float*)d_in[0];
    const float* Wf = (const float*)d_in[1];
    const float* bf = (const float*)d_in[2];
    const float* Wi = (const float*)d_in[3];
    const float* bi = (const float*)d_in[4];
    const float* Wc = (const float*)d_in[5];
    const float* bc = (const float*)d_in[6];
    const float* Wo = (const float*)d_in[7];
    const float* bo = (const float*)d_in[8];
    const float* Wout = (const float*)d_in[9];
    const float* bout = (const float*)d_in[10];
    float* out = (float*)d_out;

    static bool attr_done = false;
    if (!attr_done) {
        cudaFuncSetAttribute(phase1_mma, cudaFuncAttributeMaxDynamicSharedMemorySize, P1_SMEM);
        cudaFuncSetAttribute(lstm_persistent, cudaFuncAttributeMaxDynamicSharedMemorySize, PS_SMEM);
        attr_done = true;
    }

    pack_x<<<(unsigned)((size_t)Tt * Bb * Ii / 4 / 256), 256>>>(inputs);
    pack_w<<<Ii + Hh, 256>>>(Wf, bf, Wi, bi, Wc, bc, Wo, bo);
    zero_state<<<(Bb * Hh + 255) / 256, 256>>>();

    // Phase 1: M = 131072, N = 2048, K = 256, 128x128 tiles
    phase1_mma<<<dim3(G4 / 128, (Tt * Bb) / 128), 256, P1_SMEM>>>();

    // Persistent recurrence: 16 n-tiles x 8 b-groups = 128 CTAs, single wave
    lstm_persistent<<<dim3(G4 / 128, Bb / 32), 128, PS_SMEM>>>();

    final_head<<<Bb, 256>>>(Wout, bout, out);
}